// round 16
// baseline (speedup 1.0000x reference)
#include <cuda_runtime.h>
#include <cstdint>

#define NTOT 500000
#define CT 64
#define THREADS 512
#define NTILES ((NTOT + CT - 1) / CT)

#define O_WT 0
#define O_WG 32768
#define O_X  65536     // 2 x 16KB, parity buffers
#define O_M  98304     // 2 x 16KB
#define O_Y  131072    // 16KB
#define SMEM_BYTES 147456

__device__ __forceinline__ uint32_t pack_f16x2(float lo, float hi) {
    uint32_t w; asm("cvt.rn.f16x2.f32 %0, %1, %2;" : "=r"(w) : "f"(hi), "f"(lo)); return w;
}
__device__ __forceinline__ void mma16(float* c,
    uint32_t a0, uint32_t a1, uint32_t a2, uint32_t a3, uint32_t b0, uint32_t b1) {
    asm volatile("mma.sync.aligned.m16n8k16.row.col.f32.f16.f16.f32 "
        "{%0,%1,%2,%3}, {%4,%5,%6,%7}, {%8,%9}, {%0,%1,%2,%3};"
        : "+f"(c[0]), "+f"(c[1]), "+f"(c[2]), "+f"(c[3])
        : "r"(a0), "r"(a1), "r"(a2), "r"(a3), "r"(b0), "r"(b1));
}
#define LDS32(r,a) asm volatile("ld.shared.u32 %0, [%1];" : "=r"(r) : "r"(a))
#define STS64(a,v0,v1) asm volatile("st.shared.v2.u32 [%0], {%1,%2};" :: "r"(a), "r"(v0), "r"(v1))
#define STS32(a,v) asm volatile("st.shared.u32 [%0], %1;" :: "r"(a), "r"(v))

extern "C" __global__ void zero_out_kernel(float* __restrict__ out) {
    int i = blockIdx.x * blockDim.x + threadIdx.x;
    if (i < 128 * 128) out[i] = 0.0f;
}

// X tile: [64 m][64 f16x2 words], 256B rows, word w stored at w ^ ((m&7)<<2)
#define LDG_XW(wq, tile, valid) do { const int nn0 = (tile) * CT;               \
    _Pragma("unroll") for (int h = 0; h < 2; h++) {                             \
        int row = warp + ((((wq) << 1) + h) << 4); int n = nn0 + row;           \
        xr[h] = ((valid) && n < NTOT)                                           \
            ? *(const float4*)(nodes + (size_t)n * 128 + (lane << 2))           \
            : make_float4(0.f, 0.f, 0.f, 0.f); } } while (0)

#define STS_XW(wq, base) do {                                                   \
    _Pragma("unroll") for (int h = 0; h < 2; h++) {                             \
        int row = warp + ((((wq) << 1) + h) << 4);                              \
        uint32_t kp = (uint32_t)((lane << 1) ^ ((row & 7) << 2));               \
        STS64((base) + (row << 8) + (kp << 2),                                  \
              pack_f16x2(xr[h].x, xr[h].y), pack_f16x2(xr[h].z, xr[h].w)); } } while (0)

// mask tile: [128 b][32 words], 128B rows, word w at w ^ ((b&7)<<2)
#define LDG_MW(wq, tile) do { const int nn0 = (tile) * CT;                      \
    _Pragma("unroll") for (int h = 0; h < 2; h++) {                             \
        int b = (warp << 1) + (lane >> 4) + ((((wq) << 1) + h) << 5);           \
        int k0 = (lane & 15) << 2;                                              \
        mr[h] = (nn0 + k0) < NTOT                                               \
            ? *(const int4*)(masks + (size_t)b * NTOT + nn0 + k0)               \
            : make_int4(0, 0, 0, 0); } } while (0)

#define STS_MW(wq, base) do {                                                   \
    _Pragma("unroll") for (int h = 0; h < 2; h++) {                             \
        int b = (warp << 1) + (lane >> 4) + ((((wq) << 1) + h) << 5);           \
        uint32_t kp = (uint32_t)(((lane & 15) << 1) ^ ((b & 7) << 2));          \
        STS64((base) + (b << 7) + (kp << 2),                                    \
              (uint32_t)mr[h].x * 0x3C00u + (uint32_t)mr[h].y * 0x3C000000u,    \
              (uint32_t)mr[h].z * 0x3C00u + (uint32_t)mr[h].w * 0x3C000000u); } } while (0)

#define ASTEP(ks) do {                                                          \
    const uint32_t w0 = (uint32_t)(((8 * (ks) + tg) ^ xk) << 2);                \
    const uint32_t w1 = (uint32_t)(((8 * (ks) + tg + 4) ^ xk) << 2);            \
    uint32_t a0,a1,a2,a3,a4,a5,a6,a7;                                           \
    LDS32(a0, xrd + w0);          LDS32(a1, xrd + 0x800 + w0);                  \
    LDS32(a2, xrd + w1);          LDS32(a3, xrd + 0x800 + w1);                  \
    LDS32(a4, xrd + 0x1000 + w0); LDS32(a5, xrd + 0x1800 + w0);                 \
    LDS32(a6, xrd + 0x1000 + w1); LDS32(a7, xrd + 0x1800 + w1);                 \
    _Pragma("unroll") for (int j = 0; j < 2; j++) {                             \
        uint32_t d0, d1, g0, g1;                                                \
        LDS32(d0, wtb + (j << 11) + w0); LDS32(d1, wtb + (j << 11) + w1);       \
        LDS32(g0, wgb + (j << 11) + w0); LDS32(g1, wgb + (j << 11) + w1);       \
        mma16(aD[0][j], a0, a1, a2, a3, d0, d1);                                \
        mma16(aD[1][j], a4, a5, a6, a7, d0, d1);                                \
        mma16(aG[0][j], a0, a1, a2, a3, g0, g1);                                \
        mma16(aG[1][j], a4, a5, a6, a7, g0, g1); } } while (0)

#define BSTEP(kk) do {                                                          \
    const uint32_t w0 = (uint32_t)(((8 * (kk) + tg) ^ xk) << 2);                \
    const uint32_t w1 = (uint32_t)(((8 * (kk) + tg + 4) ^ xk) << 2);            \
    uint32_t m0,m1,m2,m3,m4,m5,m6,m7;                                           \
    LDS32(m0, mrd + w0);         LDS32(m1, mrd + 0x400 + w0);                   \
    LDS32(m2, mrd + w1);         LDS32(m3, mrd + 0x400 + w1);                   \
    LDS32(m4, mrd + 0x800 + w0); LDS32(m5, mrd + 0xC00 + w0);                   \
    LDS32(m6, mrd + 0x800 + w1); LDS32(m7, mrd + 0xC00 + w1);                   \
    _Pragma("unroll") for (int j = 0; j < 4; j++) {                             \
        uint32_t y0, y1;                                                        \
        LDS32(y0, ybb + (j << 10) + w0); LDS32(y1, ybb + (j << 10) + w1);       \
        mma16(pc[0][j], m0, m1, m2, m3, y0, y1);                                \
        mma16(pc[1][j], m4, m5, m6, m7, y0, y1); } } while (0)

#define EPILOGUE() do {                                                         \
    _Pragma("unroll") for (int s = 0; s < 2; s++)                               \
    _Pragma("unroll") for (int j = 0; j < 2; j++)                               \
    _Pragma("unroll") for (int r = 0; r < 4; r++) {                             \
        int r1 = r & 1, r2 = r >> 1;                                            \
        int m = mbase + 16 * s + 8 * r2 + gid;                                  \
        int n = nb + 8 * j + 2 * tg + r1;                                       \
        float d  = aD[s][j][r] + btv[j][r1];                                    \
        float gl = aG[s][j][r] + bgv[j][r1];                                    \
        float y = d / (1.0f + __expf(-gl));                                     \
        float yp = __shfl_xor_sync(0xffffffffu, y, 4);                          \
        if (!(gid & 1))                                                         \
            STS32(sy + (n << 7) + (((uint32_t)(((m >> 1) ^ ((n & 7) << 2)))) << 2), \
                  pack_f16x2(y, yp)); } } while (0)

#define ZACC() do {                                                             \
    _Pragma("unroll") for (int s = 0; s < 2; s++)                               \
    _Pragma("unroll") for (int j = 0; j < 2; j++)                               \
    _Pragma("unroll") for (int r = 0; r < 4; r++) {                             \
        aD[s][j][r] = 0.0f; aG[s][j][r] = 0.0f; } } while (0)

extern "C" __global__ void __launch_bounds__(THREADS, 1)
agg_kernel(const float* __restrict__ nodes, const int* __restrict__ masks,
           const float* __restrict__ Wt, const float* __restrict__ bt,
           const float* __restrict__ Wg, const float* __restrict__ bg,
           float* __restrict__ out) {
    extern __shared__ char smem[];
    const uint32_t sb = (uint32_t)__cvta_generic_to_shared(smem);
    const uint32_t sy = sb + O_Y;

    const int tid = threadIdx.x, warp = tid >> 5, lane = tid & 31;
    const int tg = lane & 3, gid = lane >> 2;
    const int stride = gridDim.x;
    const int mbase = (warp & 1) << 5;        // A: 32m x 16n x2 mats
    const int nb    = (warp >> 1) << 4;
    const int pb = warp & 3, pd = warp >> 2;  // B: 32b x 32d
    const uint32_t xk = (uint32_t)gid << 2;

    const uint32_t wtb = sb + O_WT + ((uint32_t)(nb + gid) << 8);
    const uint32_t wgb = sb + O_WG + ((uint32_t)(nb + gid) << 8);
    const uint32_t ybb = sy + ((uint32_t)((pd << 5) + gid) << 7);

    // W -> f16x2 [n][k-pair] (one time)
    for (int i = tid; i < 8192; i += THREADS) {
        int n = i & 127, kp = i >> 7;
        uint32_t off = ((uint32_t)n << 8) + (((uint32_t)(kp ^ ((n & 7) << 2))) << 2);
        STS32(sb + O_WT + off, pack_f16x2(Wt[(2 * kp) * 128 + n], Wt[(2 * kp + 1) * 128 + n]));
        STS32(sb + O_WG + off, pack_f16x2(Wg[(2 * kp) * 128 + n], Wg[(2 * kp + 1) * 128 + n]));
    }
    float btv[2][2], bgv[2][2];
#pragma unroll
    for (int j = 0; j < 2; j++)
#pragma unroll
        for (int r1 = 0; r1 < 2; r1++) {
            int n = nb + 8 * j + 2 * tg + r1;
            btv[j][r1] = bt[n]; bgv[j][r1] = bg[n];
        }

    float pc[2][4][4];
#pragma unroll
    for (int s = 0; s < 2; s++)
#pragma unroll
        for (int j = 0; j < 4; j++)
#pragma unroll
            for (int r = 0; r < 4; r++) pc[s][j][r] = 0.0f;
    float aD[2][2][4], aG[2][2][4];
    float4 xr[2]; int4 mr[2];

    int t = blockIdx.x;
    // prologue: X(t) -> X16 buffer 0 (latency exposed once)
    LDG_XW(0, t, 1); STS_XW(0, sb + O_X);
    LDG_XW(1, t, 1); STS_XW(1, sb + O_X);
    __syncthreads();

    // peel: GEMM(t) only; write X(t+1), M(t) into parity-1 buffers
    uint32_t xrd = sb + O_X + ((uint32_t)(mbase + gid) << 8);
    uint32_t mrd;
    ZACC();
    {
        int tn = t + stride, vx = tn < NTILES;
        LDG_XW(0, tn, vx); ASTEP(0); ASTEP(1); STS_XW(0, sb + O_X + 16384);
        LDG_XW(1, tn, vx); ASTEP(2); ASTEP(3); STS_XW(1, sb + O_X + 16384);
        LDG_MW(0, t);      ASTEP(4); ASTEP(5); STS_MW(0, sb + O_M + 16384);
        LDG_MW(1, t);      ASTEP(6); ASTEP(7); STS_MW(1, sb + O_M + 16384);
    }
    __syncthreads();
    EPILOGUE();
    t += stride;
    int p = 1;

    for (; t < NTILES; t += stride, p ^= 1) {
        __syncthreads();   // X16[p](t), M16[p](t-1), Y(t-1) visible
        xrd = sb + O_X + ((uint32_t)p << 14) + ((uint32_t)(mbase + gid) << 8);
        mrd = sb + O_M + ((uint32_t)p << 14) + ((uint32_t)((pb << 5) + gid) << 7);
        const uint32_t xwv = sb + O_X + ((uint32_t)(p ^ 1) << 14);
        const uint32_t mwv = sb + O_M + ((uint32_t)(p ^ 1) << 14);
        ZACC();
        int tn = t + stride, vx = tn < NTILES;
        LDG_XW(0, tn, vx); ASTEP(0); ASTEP(1); BSTEP(0); STS_XW(0, xwv);
        LDG_XW(1, tn, vx); ASTEP(2); ASTEP(3); BSTEP(1); STS_XW(1, xwv);
        LDG_MW(0, t);      ASTEP(4); ASTEP(5); BSTEP(2); STS_MW(0, mwv);
        LDG_MW(1, t);      ASTEP(6); ASTEP(7); BSTEP(3); STS_MW(1, mwv);
        __syncthreads();   // reads of p done; next iter writes p safely
        EPILOGUE();        // Y(t)
    }

    // drain: pool(t_last) from M16[p] + Y(t_last)
    __syncthreads();
    mrd = sb + O_M + ((uint32_t)p << 14) + ((uint32_t)((pb << 5) + gid) << 7);
    BSTEP(0); BSTEP(1); BSTEP(2); BSTEP(3);

#pragma unroll
    for (int s = 0; s < 2; s++)
#pragma unroll
        for (int j = 0; j < 4; j++)
#pragma unroll
            for (int r = 0; r < 4; r++) {
                int b = (pb << 5) + 16 * s + 8 * (r >> 1) + gid;
                int c = (pd << 5) + 8 * j + 2 * tg + (r & 1);
                atomicAdd(&out[b * 128 + c], pc[s][j][r]);
            }
}

extern "C" void kernel_launch(void* const* d_in, const int* in_sizes, int n_in,
                              void* d_out, int out_size) {
    (void)in_sizes; (void)n_in; (void)out_size;
    cudaFuncSetAttribute(agg_kernel, cudaFuncAttributeMaxDynamicSharedMemorySize, SMEM_BYTES);
    zero_out_kernel<<<32, 512>>>((float*)d_out);
    agg_kernel<<<148, THREADS, SMEM_BYTES>>>(
        (const float*)d_in[0], (const int*)d_in[1], (const float*)d_in[2],
        (const float*)d_in[3], (const float*)d_in[4], (const float*)d_in[5], (float*)d_out);
}